// round 1
// baseline (speedup 1.0000x reference)
#include <cuda_runtime.h>
#include <cuda_bf16.h>

// ---------------------------------------------------------------------------
// DNFNetLocalization: out = softmax(sigmoid(T) * exp(-||(x-mu)*sigma||_2), axis=formulas)
// Reformulated: dist2[b,f] = dot(A'[b], B'[f]) + c[f], A'=[x^2, x], B'=[s^2, -2 s^2 mu]
// ---------------------------------------------------------------------------

#define BATCH 2048
#define NF    1024
#define DIM   256
#define KK    512        // 2*DIM

// scratch (device globals: allocation-free)
__device__ float g_A[BATCH * KK];   // 4 MB
__device__ float g_B[NF * KK];      // 2 MB
__device__ float g_c[NF];

// ---------------------------------------------------------------------------
__global__ void prep_A_kernel(const float* __restrict__ x) {
    int b = blockIdx.x;          // 2048
    int d = threadIdx.x;         // 256
    float v = x[b * DIM + d];
    g_A[b * KK + d]       = v * v;
    g_A[b * KK + DIM + d] = v;
}

__global__ void prep_B_kernel(const float* __restrict__ mu, const float* __restrict__ sigma) {
    int f = blockIdx.x;          // 1024
    int d = threadIdx.x;         // 256
    float s = sigma[f * DIM + d];
    float m = mu[f * DIM + d];
    float w = s * s;
    g_B[f * KK + d]       = w;
    g_B[f * KK + DIM + d] = -2.0f * w * m;

    __shared__ float red[256];
    red[d] = w * m * m;
    __syncthreads();
    #pragma unroll
    for (int off = 128; off > 0; off >>= 1) {
        if (d < off) red[d] += red[d + off];
        __syncthreads();
    }
    if (d == 0) g_c[f] = red[0];
}

// ---------------------------------------------------------------------------
// packed f32x2 helpers (Blackwell FFMA2 path, PTX-only)
__device__ __forceinline__ unsigned long long dup2(float v) {
    unsigned long long r;
    asm("mov.b64 %0, {%1, %1};" : "=l"(r) : "f"(v));
    return r;
}
__device__ __forceinline__ void ffma2(unsigned long long& d,
                                      unsigned long long a,
                                      unsigned long long b) {
    asm("fma.rn.f32x2 %0, %1, %2, %0;" : "+l"(d) : "l"(a), "l"(b));
}

#define BM 128
#define BN 128
#define BK 8
#define NKT (KK / BK)     // 64
#define SLD 132           // padded smem row stride (conflict-free stores)

__global__ __launch_bounds__(256)
void gemm_epi_kernel(const float* __restrict__ tptr, float* __restrict__ out) {
    __shared__ __align__(16) float As[2][BK][SLD];
    __shared__ __align__(16) float Bs[2][BK][SLD];

    const int tid  = threadIdx.x;
    const int bM   = blockIdx.y * BM;
    const int bN   = blockIdx.x * BN;

    // global-load mapping: 2 threads per row, one float4 each
    const int lrow = tid >> 1;          // 0..127
    const int lk4  = (tid & 1) * 4;     // 0 or 4
    const float* Ag = g_A + (size_t)(bM + lrow) * KK + lk4;
    const float* Bg = g_B + (size_t)(bN + lrow) * KK + lk4;

    // compute mapping: 4+4 split micro-tile
    const int tx = tid & 15;
    const int ty = tid >> 4;
    const int m0 = ty * 4;              // rows m0..m0+3 and m0+64..m0+67
    const int n0 = tx * 4;              // cols n0..n0+3 and n0+64..n0+67

    unsigned long long acc[4][8];
    #pragma unroll
    for (int i = 0; i < 4; ++i)
        #pragma unroll
        for (int j = 0; j < 8; ++j) acc[i][j] = 0ULL;

    // preload tile 0
    {
        float4 av = *(const float4*)(Ag);
        float4 bv = *(const float4*)(Bg);
        As[0][lk4 + 0][lrow] = av.x; As[0][lk4 + 1][lrow] = av.y;
        As[0][lk4 + 2][lrow] = av.z; As[0][lk4 + 3][lrow] = av.w;
        Bs[0][lk4 + 0][lrow] = bv.x; Bs[0][lk4 + 1][lrow] = bv.y;
        Bs[0][lk4 + 2][lrow] = bv.z; Bs[0][lk4 + 3][lrow] = bv.w;
    }
    __syncthreads();

    for (int kt = 0; kt < NKT; ++kt) {
        const int cur = kt & 1;
        const int nxt = cur ^ 1;

        float4 an, bn;
        if (kt + 1 < NKT) {
            an = *(const float4*)(Ag + (kt + 1) * BK);
            bn = *(const float4*)(Bg + (kt + 1) * BK);
        }

        #pragma unroll
        for (int k = 0; k < BK; ++k) {
            ulonglong2 aLo = *(const ulonglong2*)&As[cur][k][m0];
            ulonglong2 aHi = *(const ulonglong2*)&As[cur][k][m0 + 64];
            float4 b0 = *(const float4*)&Bs[cur][k][n0];
            float4 b1 = *(const float4*)&Bs[cur][k][n0 + 64];

            unsigned long long a2[4] = { aLo.x, aLo.y, aHi.x, aHi.y };
            unsigned long long bb[8] = {
                dup2(b0.x), dup2(b0.y), dup2(b0.z), dup2(b0.w),
                dup2(b1.x), dup2(b1.y), dup2(b1.z), dup2(b1.w)
            };
            #pragma unroll
            for (int mp = 0; mp < 4; ++mp)
                #pragma unroll
                for (int n = 0; n < 8; ++n)
                    ffma2(acc[mp][n], a2[mp], bb[n]);
        }

        if (kt + 1 < NKT) {
            As[nxt][lk4 + 0][lrow] = an.x; As[nxt][lk4 + 1][lrow] = an.y;
            As[nxt][lk4 + 2][lrow] = an.z; As[nxt][lk4 + 3][lrow] = an.w;
            Bs[nxt][lk4 + 0][lrow] = bn.x; Bs[nxt][lk4 + 1][lrow] = bn.y;
            Bs[nxt][lk4 + 2][lrow] = bn.z; Bs[nxt][lk4 + 3][lrow] = bn.w;
        }
        __syncthreads();
    }

    // ---------------- epilogue ----------------
    const float t    = *tptr;
    const float sigT = 1.0f / (1.0f + __expf(-t));

    float cf[8];
    #pragma unroll
    for (int n = 0; n < 4; ++n) {
        cf[n]     = g_c[bN + n0 + n];
        cf[n + 4] = g_c[bN + n0 + 64 + n];
    }

    #pragma unroll
    for (int mp = 0; mp < 4; ++mp) {
        const int mbase = bM + ((mp < 2) ? (m0 + mp * 2) : (m0 + 64 + (mp - 2) * 2));
        #pragma unroll
        for (int half = 0; half < 2; ++half) {
            const int gm = mbase + half;
            float v[8];
            #pragma unroll
            for (int n = 0; n < 8; ++n) {
                float2 p = *reinterpret_cast<float2*>(&acc[mp][n]);
                float d2 = (half ? p.y : p.x) + cf[n];
                float dist = sqrtf(fmaxf(d2, 0.0f));
                v[n] = __expf(sigT * __expf(-dist));
            }
            float4 o0 = make_float4(v[0], v[1], v[2], v[3]);
            float4 o1 = make_float4(v[4], v[5], v[6], v[7]);
            *reinterpret_cast<float4*>(&out[(size_t)gm * NF + bN + n0])      = o0;
            *reinterpret_cast<float4*>(&out[(size_t)gm * NF + bN + n0 + 64]) = o1;
        }
    }
}

// ---------------------------------------------------------------------------
__global__ void normalize_kernel(float* __restrict__ out) {
    const int b   = blockIdx.x;       // 2048
    const int tid = threadIdx.x;      // 256
    float4 v = *reinterpret_cast<float4*>(&out[(size_t)b * NF + tid * 4]);
    float s = v.x + v.y + v.z + v.w;

    #pragma unroll
    for (int off = 16; off > 0; off >>= 1)
        s += __shfl_xor_sync(0xFFFFFFFFu, s, off);

    __shared__ float ws[8];
    if ((tid & 31) == 0) ws[tid >> 5] = s;
    __syncthreads();
    if (tid == 0) {
        float tot = 0.0f;
        #pragma unroll
        for (int i = 0; i < 8; ++i) tot += ws[i];
        ws[0] = tot;
    }
    __syncthreads();
    const float inv = 1.0f / ws[0];
    v.x *= inv; v.y *= inv; v.z *= inv; v.w *= inv;
    *reinterpret_cast<float4*>(&out[(size_t)b * NF + tid * 4]) = v;
}

// ---------------------------------------------------------------------------
extern "C" void kernel_launch(void* const* d_in, const int* in_sizes, int n_in,
                              void* d_out, int out_size) {
    const float* x     = (const float*)d_in[0];   // (2048, 256)
    const float* mu    = (const float*)d_in[1];   // (1024, 256)
    const float* sigma = (const float*)d_in[2];   // (1, 1024, 256)
    const float* temp  = (const float*)d_in[3];   // scalar
    float* out = (float*)d_out;                   // (2048, 1024)

    prep_A_kernel<<<BATCH, DIM>>>(x);
    prep_B_kernel<<<NF, DIM>>>(mu, sigma);
    gemm_epi_kernel<<<dim3(NF / BN, BATCH / BM), 256>>>(temp, out);
    normalize_kernel<<<BATCH, 256>>>(out);
}

// round 3
// speedup vs baseline: 2.5614x; 2.5614x over previous
#include <cuda_runtime.h>
#include <cuda_bf16.h>
#include <cstdint>

// ---------------------------------------------------------------------------
// DNFNetLocalization via mma.sync bf16 GEMM (sm_103 baseline PTX, no 'a' features)
//   dist2[b,f] = dot(A'[b], B'[f]) + c[f],  A'=[x^2, x]  B'=[s^2, -2 s^2 mu]
//   out = softmax_f( exp( sigmoid(T) * exp(-sqrt(dist2)) ) )
// ---------------------------------------------------------------------------

#define BATCH 2048
#define NF    1024
#define DIM   256
#define KK    512        // 2*DIM

__device__ __nv_bfloat16 g_A[BATCH * KK];   // 2 MB
__device__ __nv_bfloat16 g_B[NF * KK];      // 1 MB
__device__ float g_c[NF];

// ===========================================================================
// prep kernels
// ===========================================================================
__global__ void prep_A_kernel(const float* __restrict__ x) {
    int b = blockIdx.x;          // 2048
    int d = threadIdx.x;         // 256
    float v = x[b * DIM + d];
    g_A[b * KK + d]       = __float2bfloat16_rn(v * v);
    g_A[b * KK + DIM + d] = __float2bfloat16_rn(v);
}

__global__ void prep_B_kernel(const float* __restrict__ mu, const float* __restrict__ sigma) {
    int f = blockIdx.x;          // 1024
    int d = threadIdx.x;         // 256
    float s = sigma[f * DIM + d];
    float m = mu[f * DIM + d];
    float w = s * s;
    g_B[f * KK + d]       = __float2bfloat16_rn(w);
    g_B[f * KK + DIM + d] = __float2bfloat16_rn(-2.0f * w * m);

    __shared__ float red[256];
    red[d] = w * m * m;
    __syncthreads();
    #pragma unroll
    for (int off = 128; off > 0; off >>= 1) {
        if (d < off) red[d] += red[d + off];
        __syncthreads();
    }
    if (d == 0) g_c[f] = red[0];
}

// ===========================================================================
// mma.sync GEMM (BM=128, BN=128, BK=32, 8 warps, warp tile 64x32)
// ===========================================================================
#define BM 128
#define BN 128
#define BK 32
#define PITCH 40            // halves per smem row (32 + 8 pad); 80B, 16B-aligned
#define NCHUNK (KK / BK)    // 16

__device__ __forceinline__ uint32_t smem_addr_u32(const void* p) {
    return (uint32_t)__cvta_generic_to_shared(p);
}

#define CP_ASYNC16(saddr, gptr) \
    asm volatile("cp.async.cg.shared.global [%0], [%1], 16;" \
                 :: "r"(saddr), "l"(gptr))
#define CP_COMMIT() asm volatile("cp.async.commit_group;")
#define CP_WAIT0()  asm volatile("cp.async.wait_group 0;" ::: "memory")

#define LDMATRIX_X4(r0, r1, r2, r3, addr) \
    asm volatile("ldmatrix.sync.aligned.m8n8.x4.shared.b16 {%0,%1,%2,%3}, [%4];" \
                 : "=r"(r0), "=r"(r1), "=r"(r2), "=r"(r3) : "r"(addr))

#define MMA_BF16(c0, c1, c2, c3, a0, a1, a2, a3, b0, b1) \
    asm volatile("mma.sync.aligned.m16n8k16.row.col.f32.bf16.bf16.f32 " \
                 "{%0,%1,%2,%3}, {%4,%5,%6,%7}, {%8,%9}, {%0,%1,%2,%3};" \
                 : "+f"(c0), "+f"(c1), "+f"(c2), "+f"(c3) \
                 : "r"(a0), "r"(a1), "r"(a2), "r"(a3), "r"(b0), "r"(b1))

__device__ __forceinline__ float fsqrt_approx(float x) {
    float r;
    asm("sqrt.approx.f32 %0, %1;" : "=f"(r) : "f"(x));
    return r;
}

__global__ __launch_bounds__(256, 1)
void gemm_mma_kernel(const float* __restrict__ tptr, float* __restrict__ out) {
    __shared__ __nv_bfloat16 As[2][BM * PITCH];   // 2 * 10240 B
    __shared__ __nv_bfloat16 Bs[2][BN * PITCH];   // 2 * 10240 B

    const int tid  = threadIdx.x;
    const int wid  = tid >> 5;
    const int lane = tid & 31;
    const int bN   = blockIdx.x * BN;
    const int bM   = blockIdx.y * BM;

    const int warpM = wid & 1;        // 0..1  -> 64 rows
    const int warpN = wid >> 1;       // 0..3  -> 32 cols

    // ---- cp.async load mapping: 2 vectors (16B = 8 halves) per thread per tile ----
    // tile chunk = 128 rows x 32 halves (64 B) -> 512 vectors; vid = tid + i*256
    const __nv_bfloat16* Agp = g_A + (size_t)bM * KK;
    const __nv_bfloat16* Bgp = g_B + (size_t)bN * KK;

    auto load_chunk = [&](int kc, int buf) {
        #pragma unroll
        for (int i = 0; i < 2; ++i) {
            int vid = tid + i * 256;
            int row = vid >> 2;            // 0..127
            int v   = vid & 3;             // 0..3 (16B each)
            uint32_t sa = smem_addr_u32(&As[buf][row * PITCH + v * 8]);
            uint32_t sb = smem_addr_u32(&Bs[buf][row * PITCH + v * 8]);
            CP_ASYNC16(sa, Agp + (size_t)row * KK + kc * BK + v * 8);
            CP_ASYNC16(sb, Bgp + (size_t)row * KK + kc * BK + v * 8);
        }
        CP_COMMIT();
    };

    // ---- ldmatrix address components ----
    // A (16x16, row-major): lanes 0-15 -> rows 0..15 @k0 ; lanes 16-31 -> rows @k0+8
    const int a_row  = lane & 15;
    const int a_koff = (lane >> 4) << 3;
    // B (two 8-col tiles per x4): lanes 0-7: n0+l @k0 ; 8-15: n0+l @k0+8 ;
    //                             16-23: n0+8+l @k0 ; 24-31: n0+8+l @k0+8
    const int b_nrow = (lane & 7) + ((lane >> 4) << 3);
    const int b_koff = ((lane >> 3) & 1) << 3;

    float acc[4][4][4];
    #pragma unroll
    for (int m = 0; m < 4; ++m)
        #pragma unroll
        for (int n = 0; n < 4; ++n)
            #pragma unroll
            for (int j = 0; j < 4; ++j) acc[m][n][j] = 0.0f;

    load_chunk(0, 0);

    for (int kc = 0; kc < NCHUNK; ++kc) {
        CP_WAIT0();
        __syncthreads();
        const int cur = kc & 1;
        if (kc + 1 < NCHUNK) load_chunk(kc + 1, cur ^ 1);

        #pragma unroll
        for (int ks = 0; ks < 2; ++ks) {             // two k16 steps per chunk
            const int k0 = ks * 16;

            uint32_t af[4][4];
            #pragma unroll
            for (int mt = 0; mt < 4; ++mt) {
                uint32_t addr = smem_addr_u32(
                    &As[cur][(warpM * 64 + mt * 16 + a_row) * PITCH + k0 + a_koff]);
                LDMATRIX_X4(af[mt][0], af[mt][1], af[mt][2], af[mt][3], addr);
            }

            uint32_t bf[4][2];
            #pragma unroll
            for (int np = 0; np < 2; ++np) {         // each x4 covers 2 n-tiles
                uint32_t addr = smem_addr_u32(
                    &Bs[cur][(warpN * 32 + np * 16 + b_nrow) * PITCH + k0 + b_koff]);
                LDMATRIX_X4(bf[np * 2][0], bf[np * 2][1],
                            bf[np * 2 + 1][0], bf[np * 2 + 1][1], addr);
            }

            #pragma unroll
            for (int mt = 0; mt < 4; ++mt)
                #pragma unroll
                for (int nt = 0; nt < 4; ++nt)
                    MMA_BF16(acc[mt][nt][0], acc[mt][nt][1],
                             acc[mt][nt][2], acc[mt][nt][3],
                             af[mt][0], af[mt][1], af[mt][2], af[mt][3],
                             bf[nt][0], bf[nt][1]);
        }
        __syncthreads();
    }

    // ------------------- fused epilogue -------------------
    const float t    = *tptr;
    const float sigT = 1.0f / (1.0f + __expf(-t));

    const int g  = lane >> 2;       // 0..7
    const int tq = lane & 3;        // 0..3

    float2 cpair[4];
    #pragma unroll
    for (int nt = 0; nt < 4; ++nt) {
        int col = bN + warpN * 32 + nt * 8 + 2 * tq;
        cpair[nt] = *reinterpret_cast<const float2*>(&g_c[col]);
    }

    #pragma unroll
    for (int mt = 0; mt < 4; ++mt) {
        const int r0 = bM + warpM * 64 + mt * 16 + g;
        #pragma unroll
        for (int nt = 0; nt < 4; ++nt) {
            const int col = bN + warpN * 32 + nt * 8 + 2 * tq;
            float2 o0, o1;
            {
                float d2 = fmaxf(acc[mt][nt][0] + cpair[nt].x, 0.0f);
                o0.x = __expf(sigT * __expf(-fsqrt_approx(d2)));
                d2 = fmaxf(acc[mt][nt][1] + cpair[nt].y, 0.0f);
                o0.y = __expf(sigT * __expf(-fsqrt_approx(d2)));
                d2 = fmaxf(acc[mt][nt][2] + cpair[nt].x, 0.0f);
                o1.x = __expf(sigT * __expf(-fsqrt_approx(d2)));
                d2 = fmaxf(acc[mt][nt][3] + cpair[nt].y, 0.0f);
                o1.y = __expf(sigT * __expf(-fsqrt_approx(d2)));
            }
            *reinterpret_cast<float2*>(&out[(size_t)r0 * NF + col])       = o0;
            *reinterpret_cast<float2*>(&out[(size_t)(r0 + 8) * NF + col]) = o1;
        }
    }
}

// ===========================================================================
// normalize: one warp per row, no smem
// ===========================================================================
__global__ __launch_bounds__(256)
void normalize_kernel(float* __restrict__ out) {
    const int gw   = (blockIdx.x * 256 + threadIdx.x) >> 5;   // 0..2047
    const int lane = threadIdx.x & 31;
    float* rp = out + (size_t)gw * NF;

    float4 v[8];
    float s = 0.0f;
    #pragma unroll
    for (int j = 0; j < 8; ++j) {
        v[j] = *reinterpret_cast<float4*>(rp + (j * 32 + lane) * 4);
        s += (v[j].x + v[j].y) + (v[j].z + v[j].w);
    }
    #pragma unroll
    for (int off = 16; off > 0; off >>= 1)
        s += __shfl_xor_sync(0xFFFFFFFFu, s, off);
    const float inv = 1.0f / s;
    #pragma unroll
    for (int j = 0; j < 8; ++j) {
        v[j].x *= inv; v[j].y *= inv; v[j].z *= inv; v[j].w *= inv;
        *reinterpret_cast<float4*>(rp + (j * 32 + lane) * 4) = v[j];
    }
}

// ===========================================================================
extern "C" void kernel_launch(void* const* d_in, const int* in_sizes, int n_in,
                              void* d_out, int out_size) {
    const float* x     = (const float*)d_in[0];   // (2048, 256)
    const float* mu    = (const float*)d_in[1];   // (1024, 256)
    const float* sigma = (const float*)d_in[2];   // (1, 1024, 256)
    const float* temp  = (const float*)d_in[3];   // scalar
    float* out = (float*)d_out;                   // (2048, 1024)

    prep_A_kernel<<<BATCH, DIM>>>(x);
    prep_B_kernel<<<NF, DIM>>>(mu, sigma);
    gemm_mma_kernel<<<dim3(NF / BN, BATCH / BM), 256>>>(temp, out);
    normalize_kernel<<<BATCH / 8, 256>>>(out);
}

// round 4
// speedup vs baseline: 3.0580x; 1.1939x over previous
#include <cuda_runtime.h>
#include <cuda_bf16.h>
#include <cstdint>

// ---------------------------------------------------------------------------
// DNFNetLocalization via mma.sync bf16 GEMM (sm_103 baseline PTX, no 'a' features)
//   dist2[b,f] = dot(A'[b], B'[f]) + c[f],  A'=[x^2, x]  B'=[s^2, -2 s^2 mu]
//   out = softmax_f( exp( sigmoid(T) * exp(-sqrt(dist2)) ) )
// ---------------------------------------------------------------------------

#define BATCH 2048
#define NF    1024
#define DIM   256
#define KK    512        // 2*DIM

__device__ __nv_bfloat16 g_A[BATCH * KK];   // 2 MB
__device__ __nv_bfloat16 g_B[NF * KK];      // 1 MB
__device__ float g_c[NF];

// ===========================================================================
// merged prep kernel: blocks [0,2048) -> A', blocks [2048,3072) -> B' + c
// ===========================================================================
__global__ __launch_bounds__(256)
void prep_kernel(const float* __restrict__ x,
                 const float* __restrict__ mu,
                 const float* __restrict__ sigma) {
    const int blk = blockIdx.x;
    const int d   = threadIdx.x;          // 256
    if (blk < BATCH) {
        float v = x[blk * DIM + d];
        g_A[blk * KK + d]       = __float2bfloat16_rn(v * v);
        g_A[blk * KK + DIM + d] = __float2bfloat16_rn(v);
    } else {
        const int f = blk - BATCH;        // 0..1023
        float s = sigma[f * DIM + d];
        float m = mu[f * DIM + d];
        float w = s * s;
        g_B[f * KK + d]       = __float2bfloat16_rn(w);
        g_B[f * KK + DIM + d] = __float2bfloat16_rn(-2.0f * w * m);

        float r = w * m * m;
        #pragma unroll
        for (int off = 16; off > 0; off >>= 1)
            r += __shfl_xor_sync(0xFFFFFFFFu, r, off);
        __shared__ float ws[8];
        if ((d & 31) == 0) ws[d >> 5] = r;
        __syncthreads();
        if (d == 0) {
            float tot = 0.0f;
            #pragma unroll
            for (int i = 0; i < 8; ++i) tot += ws[i];
            g_c[f] = tot;
        }
    }
}

// ===========================================================================
// mma.sync GEMM (BM=128, BN=128, BK=32, 8 warps, warp tile 64x32)
// 3-stage cp.async software pipeline
// ===========================================================================
#define BM 128
#define BN 128
#define BK 32
#define PITCH 40            // halves per smem row (32 + 8 pad); 80B, 16B-aligned
#define NCHUNK (KK / BK)    // 16
#define NSTAGE 3
#define TILE_H (BM * PITCH)                 // halves per tile-stage (5120)
#define SMEM_DYN (2 * NSTAGE * TILE_H * 2)  // bytes (61440)

__device__ __forceinline__ uint32_t smem_addr_u32(const void* p) {
    return (uint32_t)__cvta_generic_to_shared(p);
}

#define CP_ASYNC16(saddr, gptr) \
    asm volatile("cp.async.cg.shared.global [%0], [%1], 16;" \
                 :: "r"(saddr), "l"(gptr))
#define CP_COMMIT() asm volatile("cp.async.commit_group;")
#define CP_WAIT(n)  asm volatile("cp.async.wait_group %0;" :: "n"(n) : "memory")

#define LDMATRIX_X4(r0, r1, r2, r3, addr) \
    asm volatile("ldmatrix.sync.aligned.m8n8.x4.shared.b16 {%0,%1,%2,%3}, [%4];" \
                 : "=r"(r0), "=r"(r1), "=r"(r2), "=r"(r3) : "r"(addr))

#define MMA_BF16(c0, c1, c2, c3, a0, a1, a2, a3, b0, b1) \
    asm volatile("mma.sync.aligned.m16n8k16.row.col.f32.bf16.bf16.f32 " \
                 "{%0,%1,%2,%3}, {%4,%5,%6,%7}, {%8,%9}, {%0,%1,%2,%3};" \
                 : "+f"(c0), "+f"(c1), "+f"(c2), "+f"(c3) \
                 : "r"(a0), "r"(a1), "r"(a2), "r"(a3), "r"(b0), "r"(b1))

__device__ __forceinline__ float fsqrt_approx(float x) {
    float r;
    asm("sqrt.approx.f32 %0, %1;" : "=f"(r) : "f"(x));
    return r;
}

__global__ __launch_bounds__(256, 1)
void gemm_mma_kernel(const float* __restrict__ tptr, float* __restrict__ out) {
    extern __shared__ __nv_bfloat16 smem[];
    __nv_bfloat16* const As = smem;                       // NSTAGE * TILE_H
    __nv_bfloat16* const Bs = smem + NSTAGE * TILE_H;     // NSTAGE * TILE_H

    const int tid  = threadIdx.x;
    const int wid  = tid >> 5;
    const int lane = tid & 31;
    const int bN   = blockIdx.x * BN;
    const int bM   = blockIdx.y * BM;

    const int warpM = wid & 1;        // 0..1  -> 64 rows
    const int warpN = wid >> 1;       // 0..3  -> 32 cols

    const __nv_bfloat16* Agp = g_A + (size_t)bM * KK;
    const __nv_bfloat16* Bgp = g_B + (size_t)bN * KK;

    // per-thread load mapping: 2 x 16B vectors per matrix per chunk
    const int ld_row = tid >> 2;            // 0..63 (two row groups)
    const int ld_v   = tid & 3;             // 16B slot within 64B row chunk

    auto load_chunk = [&](int kc, int slot) {
        __nv_bfloat16* a = As + slot * TILE_H;
        __nv_bfloat16* b = Bs + slot * TILE_H;
        #pragma unroll
        for (int i = 0; i < 2; ++i) {
            int row = ld_row + i * 64;
            uint32_t sa = smem_addr_u32(a + row * PITCH + ld_v * 8);
            uint32_t sb = smem_addr_u32(b + row * PITCH + ld_v * 8);
            const __nv_bfloat16* ga = Agp + (size_t)row * KK + kc * BK + ld_v * 8;
            const __nv_bfloat16* gb = Bgp + (size_t)row * KK + kc * BK + ld_v * 8;
            CP_ASYNC16(sa, ga);
            CP_ASYNC16(sb, gb);
        }
        CP_COMMIT();
    };

    // ---- ldmatrix address components ----
    const int a_row  = lane & 15;
    const int a_koff = (lane >> 4) << 3;
    const int b_nrow = (lane & 7) + ((lane >> 4) << 3);
    const int b_koff = ((lane >> 3) & 1) << 3;

    float acc[4][4][4];
    #pragma unroll
    for (int m = 0; m < 4; ++m)
        #pragma unroll
        for (int n = 0; n < 4; ++n)
            #pragma unroll
            for (int j = 0; j < 4; ++j) acc[m][n][j] = 0.0f;

    load_chunk(0, 0);
    load_chunk(1, 1);

    for (int kc = 0; kc < NCHUNK; ++kc) {
        if (kc == NCHUNK - 1) { CP_WAIT(0); } else { CP_WAIT(1); }
        __syncthreads();

        if (kc + 2 < NCHUNK) load_chunk(kc + 2, (kc + 2) % NSTAGE);

        const __nv_bfloat16* at = As + (kc % NSTAGE) * TILE_H;
        const __nv_bfloat16* bt = Bs + (kc % NSTAGE) * TILE_H;

        #pragma unroll
        for (int ks = 0; ks < 2; ++ks) {             // two k16 steps per chunk
            const int k0 = ks * 16;

            uint32_t af[4][4];
            #pragma unroll
            for (int mt = 0; mt < 4; ++mt) {
                uint32_t addr = smem_addr_u32(
                    at + (warpM * 64 + mt * 16 + a_row) * PITCH + k0 + a_koff);
                LDMATRIX_X4(af[mt][0], af[mt][1], af[mt][2], af[mt][3], addr);
            }

            uint32_t bf[4][2];
            #pragma unroll
            for (int np = 0; np < 2; ++np) {         // each x4 covers 2 n-tiles
                uint32_t addr = smem_addr_u32(
                    bt + (warpN * 32 + np * 16 + b_nrow) * PITCH + k0 + b_koff);
                LDMATRIX_X4(bf[np * 2][0], bf[np * 2][1],
                            bf[np * 2 + 1][0], bf[np * 2 + 1][1], addr);
            }

            #pragma unroll
            for (int mt = 0; mt < 4; ++mt)
                #pragma unroll
                for (int nt = 0; nt < 4; ++nt)
                    MMA_BF16(acc[mt][nt][0], acc[mt][nt][1],
                             acc[mt][nt][2], acc[mt][nt][3],
                             af[mt][0], af[mt][1], af[mt][2], af[mt][3],
                             bf[nt][0], bf[nt][1]);
        }
    }

    // ------------------- fused epilogue -------------------
    const float t    = *tptr;
    const float sigT = 1.0f / (1.0f + __expf(-t));

    const int g  = lane >> 2;       // 0..7
    const int tq = lane & 3;        // 0..3

    float2 cpair[4];
    #pragma unroll
    for (int nt = 0; nt < 4; ++nt) {
        int col = bN + warpN * 32 + nt * 8 + 2 * tq;
        cpair[nt] = *reinterpret_cast<const float2*>(&g_c[col]);
    }

    #pragma unroll
    for (int mt = 0; mt < 4; ++mt) {
        const int r0 = bM + warpM * 64 + mt * 16 + g;
        #pragma unroll
        for (int nt = 0; nt < 4; ++nt) {
            const int col = bN + warpN * 32 + nt * 8 + 2 * tq;
            float2 o0, o1;
            {
                float d2 = fmaxf(acc[mt][nt][0] + cpair[nt].x, 0.0f);
                o0.x = __expf(sigT * __expf(-fsqrt_approx(d2)));
                d2 = fmaxf(acc[mt][nt][1] + cpair[nt].y, 0.0f);
                o0.y = __expf(sigT * __expf(-fsqrt_approx(d2)));
                d2 = fmaxf(acc[mt][nt][2] + cpair[nt].x, 0.0f);
                o1.x = __expf(sigT * __expf(-fsqrt_approx(d2)));
                d2 = fmaxf(acc[mt][nt][3] + cpair[nt].y, 0.0f);
                o1.y = __expf(sigT * __expf(-fsqrt_approx(d2)));
            }
            *reinterpret_cast<float2*>(&out[(size_t)r0 * NF + col])       = o0;
            *reinterpret_cast<float2*>(&out[(size_t)(r0 + 8) * NF + col]) = o1;
        }
    }
}

// ===========================================================================
// normalize: one block (128 threads) per row — high occupancy latency hiding
// ===========================================================================
__global__ __launch_bounds__(128)
void normalize_kernel(float* __restrict__ out) {
    const int b    = blockIdx.x;        // 0..2047
    const int tid  = threadIdx.x;       // 0..127
    const int lane = tid & 31;
    const int w    = tid >> 5;
    float* rp = out + (size_t)b * NF;

    float4 v0 = *reinterpret_cast<float4*>(rp + tid * 4);
    float4 v1 = *reinterpret_cast<float4*>(rp + 512 + tid * 4);
    float s = (v0.x + v0.y) + (v0.z + v0.w) + (v1.x + v1.y) + (v1.z + v1.w);

    #pragma unroll
    for (int off = 16; off > 0; off >>= 1)
        s += __shfl_xor_sync(0xFFFFFFFFu, s, off);

    __shared__ float ws[4];
    if (lane == 0) ws[w] = s;
    __syncthreads();
    const float tot = (ws[0] + ws[1]) + (ws[2] + ws[3]);
    const float inv = 1.0f / tot;

    v0.x *= inv; v0.y *= inv; v0.z *= inv; v0.w *= inv;
    v1.x *= inv; v1.y *= inv; v1.z *= inv; v1.w *= inv;
    *reinterpret_cast<float4*>(rp + tid * 4)       = v0;
    *reinterpret_cast<float4*>(rp + 512 + tid * 4) = v1;
}

// ===========================================================================
extern "C" void kernel_launch(void* const* d_in, const int* in_sizes, int n_in,
                              void* d_out, int out_size) {
    const float* x     = (const float*)d_in[0];   // (2048, 256)
    const float* mu    = (const float*)d_in[1];   // (1024, 256)
    const float* sigma = (const float*)d_in[2];   // (1, 1024, 256)
    const float* temp  = (const float*)d_in[3];   // scalar
    float* out = (float*)d_out;                   // (2048, 1024)

    cudaFuncSetAttribute(gemm_mma_kernel,
                         cudaFuncAttributeMaxDynamicSharedMemorySize, SMEM_DYN);

    prep_kernel<<<BATCH + NF, DIM>>>(x, mu, sigma);
    gemm_mma_kernel<<<dim3(NF / BN, BATCH / BM), 256, SMEM_DYN>>>(temp, out);
    normalize_kernel<<<BATCH, 128>>>(out);
}

// round 5
// speedup vs baseline: 3.3892x; 1.1083x over previous
#include <cuda_runtime.h>
#include <cuda_bf16.h>
#include <cstdint>

// ---------------------------------------------------------------------------
// DNFNetLocalization via mma.sync bf16 GEMM (sm_103 baseline PTX, no 'a' features)
//   dist2[b,f] = dot(A'[b], B'[f]) + c[f],  A'=[x^2, x]  B'=[s^2, -2 s^2 mu]
//   out = softmax_f( exp( sigmoid(T) * exp(-sqrt(dist2)) ) )
// ---------------------------------------------------------------------------

#define BATCH 2048
#define NF    1024
#define DIM   256
#define KK    512        // 2*DIM

__device__ __nv_bfloat16 g_A[BATCH * KK];   // 2 MB
__device__ __nv_bfloat16 g_B[NF * KK];      // 1 MB
__device__ float g_c[NF];

// ===========================================================================
// vectorized prep: 8 elems/thread, float4 loads, uint4 bf16 stores
//   blocks [0,256)    -> A' (2048 rows, 32 thr/row)
//   blocks [256,384)  -> B' + c (1024 rows, warp-per-row reduce, no smem)
// ===========================================================================
union BF8 {
    __nv_bfloat162 h[4];
    uint4 u;
};

__global__ __launch_bounds__(256)
void prep_kernel(const float* __restrict__ x,
                 const float* __restrict__ mu,
                 const float* __restrict__ sigma) {
    const int blk = blockIdx.x;
    if (blk < 256) {
        // ---- A part ----
        const int vid = blk * 256 + threadIdx.x;     // 0..65535
        const int row = vid >> 5;                    // 0..2047
        const int d0  = (vid & 31) * 8;              // 0..248
        const float4 v0 = *reinterpret_cast<const float4*>(x + row * DIM + d0);
        const float4 v1 = *reinterpret_cast<const float4*>(x + row * DIM + d0 + 4);

        BF8 sq, ln;
        sq.h[0] = __floats2bfloat162_rn(v0.x * v0.x, v0.y * v0.y);
        sq.h[1] = __floats2bfloat162_rn(v0.z * v0.z, v0.w * v0.w);
        sq.h[2] = __floats2bfloat162_rn(v1.x * v1.x, v1.y * v1.y);
        sq.h[3] = __floats2bfloat162_rn(v1.z * v1.z, v1.w * v1.w);
        ln.h[0] = __floats2bfloat162_rn(v0.x, v0.y);
        ln.h[1] = __floats2bfloat162_rn(v0.z, v0.w);
        ln.h[2] = __floats2bfloat162_rn(v1.x, v1.y);
        ln.h[3] = __floats2bfloat162_rn(v1.z, v1.w);

        *reinterpret_cast<uint4*>(g_A + row * KK + d0)       = sq.u;
        *reinterpret_cast<uint4*>(g_A + row * KK + DIM + d0) = ln.u;
    } else {
        // ---- B part ----
        const int vid = (blk - 256) * 256 + threadIdx.x;   // 0..32767
        const int row = vid >> 5;                          // 0..1023 (warp-aligned)
        const int d0  = (vid & 31) * 8;
        const float4 s0 = *reinterpret_cast<const float4*>(sigma + row * DIM + d0);
        const float4 s1 = *reinterpret_cast<const float4*>(sigma + row * DIM + d0 + 4);
        const float4 m0 = *reinterpret_cast<const float4*>(mu + row * DIM + d0);
        const float4 m1 = *reinterpret_cast<const float4*>(mu + row * DIM + d0 + 4);

        const float w0 = s0.x * s0.x, w1 = s0.y * s0.y, w2 = s0.z * s0.z, w3 = s0.w * s0.w;
        const float w4 = s1.x * s1.x, w5 = s1.y * s1.y, w6 = s1.z * s1.z, w7 = s1.w * s1.w;

        BF8 wv, bv;
        wv.h[0] = __floats2bfloat162_rn(w0, w1);
        wv.h[1] = __floats2bfloat162_rn(w2, w3);
        wv.h[2] = __floats2bfloat162_rn(w4, w5);
        wv.h[3] = __floats2bfloat162_rn(w6, w7);
        bv.h[0] = __floats2bfloat162_rn(-2.0f * w0 * m0.x, -2.0f * w1 * m0.y);
        bv.h[1] = __floats2bfloat162_rn(-2.0f * w2 * m0.z, -2.0f * w3 * m0.w);
        bv.h[2] = __floats2bfloat162_rn(-2.0f * w4 * m1.x, -2.0f * w5 * m1.y);
        bv.h[3] = __floats2bfloat162_rn(-2.0f * w6 * m1.z, -2.0f * w7 * m1.w);

        *reinterpret_cast<uint4*>(g_B + row * KK + d0)       = wv.u;
        *reinterpret_cast<uint4*>(g_B + row * KK + DIM + d0) = bv.u;

        float r = w0 * m0.x * m0.x + w1 * m0.y * m0.y
                + w2 * m0.z * m0.z + w3 * m0.w * m0.w
                + w4 * m1.x * m1.x + w5 * m1.y * m1.y
                + w6 * m1.z * m1.z + w7 * m1.w * m1.w;
        #pragma unroll
        for (int off = 16; off > 0; off >>= 1)
            r += __shfl_xor_sync(0xFFFFFFFFu, r, off);
        if ((threadIdx.x & 31) == 0) g_c[row] = r;
    }
}

// ===========================================================================
// mma.sync GEMM (BM=128, BN=128, BK=32, 8 warps, warp tile 64x32)
// 3-stage cp.async software pipeline
// ===========================================================================
#define BM 128
#define BN 128
#define BK 32
#define PITCH 40            // halves per smem row (32 + 8 pad); 80B, 16B-aligned
#define NCHUNK (KK / BK)    // 16
#define NSTAGE 3
#define TILE_H (BM * PITCH)                 // halves per tile-stage (5120)
#define SMEM_DYN (2 * NSTAGE * TILE_H * 2)  // bytes (61440)

__device__ __forceinline__ uint32_t smem_addr_u32(const void* p) {
    return (uint32_t)__cvta_generic_to_shared(p);
}

#define CP_ASYNC16(saddr, gptr) \
    asm volatile("cp.async.cg.shared.global [%0], [%1], 16;" \
                 :: "r"(saddr), "l"(gptr))
#define CP_COMMIT() asm volatile("cp.async.commit_group;")
#define CP_WAIT(n)  asm volatile("cp.async.wait_group %0;" :: "n"(n) : "memory")

#define LDMATRIX_X4(r0, r1, r2, r3, addr) \
    asm volatile("ldmatrix.sync.aligned.m8n8.x4.shared.b16 {%0,%1,%2,%3}, [%4];" \
                 : "=r"(r0), "=r"(r1), "=r"(r2), "=r"(r3) : "r"(addr))

#define MMA_BF16(c0, c1, c2, c3, a0, a1, a2, a3, b0, b1) \
    asm volatile("mma.sync.aligned.m16n8k16.row.col.f32.bf16.bf16.f32 " \
                 "{%0,%1,%2,%3}, {%4,%5,%6,%7}, {%8,%9}, {%0,%1,%2,%3};" \
                 : "+f"(c0), "+f"(c1), "+f"(c2), "+f"(c3) \
                 : "r"(a0), "r"(a1), "r"(a2), "r"(a3), "r"(b0), "r"(b1))

__device__ __forceinline__ float fsqrt_approx(float x) {
    float r;
    asm("sqrt.approx.f32 %0, %1;" : "=f"(r) : "f"(x));
    return r;
}

__global__ __launch_bounds__(256, 1)
void gemm_mma_kernel(const float* __restrict__ tptr, float* __restrict__ out) {
    extern __shared__ __nv_bfloat16 smem[];
    __nv_bfloat16* const As = smem;                       // NSTAGE * TILE_H
    __nv_bfloat16* const Bs = smem + NSTAGE * TILE_H;     // NSTAGE * TILE_H

    const int tid  = threadIdx.x;
    const int wid  = tid >> 5;
    const int lane = tid & 31;
    const int bN   = blockIdx.x * BN;
    const int bM   = blockIdx.y * BM;

    const int warpM = wid & 1;        // 0..1  -> 64 rows
    const int warpN = wid >> 1;       // 0..3  -> 32 cols

    const __nv_bfloat16* Agp = g_A + (size_t)bM * KK;
    const __nv_bfloat16* Bgp = g_B + (size_t)bN * KK;

    // per-thread load mapping: 2 x 16B vectors per matrix per chunk
    const int ld_row = tid >> 2;            // 0..63 (two row groups)
    const int ld_v   = tid & 3;             // 16B slot within 64B row chunk

    auto load_chunk = [&](int kc, int slot) {
        __nv_bfloat16* a = As + slot * TILE_H;
        __nv_bfloat16* b = Bs + slot * TILE_H;
        #pragma unroll
        for (int i = 0; i < 2; ++i) {
            int row = ld_row + i * 64;
            uint32_t sa = smem_addr_u32(a + row * PITCH + ld_v * 8);
            uint32_t sb = smem_addr_u32(b + row * PITCH + ld_v * 8);
            const __nv_bfloat16* ga = Agp + (size_t)row * KK + kc * BK + ld_v * 8;
            const __nv_bfloat16* gb = Bgp + (size_t)row * KK + kc * BK + ld_v * 8;
            CP_ASYNC16(sa, ga);
            CP_ASYNC16(sb, gb);
        }
        CP_COMMIT();
    };

    // ---- ldmatrix address components ----
    const int a_row  = lane & 15;
    const int a_koff = (lane >> 4) << 3;
    const int b_nrow = (lane & 7) + ((lane >> 4) << 3);
    const int b_koff = ((lane >> 3) & 1) << 3;

    float acc[4][4][4];
    #pragma unroll
    for (int m = 0; m < 4; ++m)
        #pragma unroll
        for (int n = 0; n < 4; ++n)
            #pragma unroll
            for (int j = 0; j < 4; ++j) acc[m][n][j] = 0.0f;

    load_chunk(0, 0);
    load_chunk(1, 1);

    for (int kc = 0; kc < NCHUNK; ++kc) {
        if (kc == NCHUNK - 1) { CP_WAIT(0); } else { CP_WAIT(1); }
        __syncthreads();

        if (kc + 2 < NCHUNK) load_chunk(kc + 2, (kc + 2) % NSTAGE);

        const __nv_bfloat16* at = As + (kc % NSTAGE) * TILE_H;
        const __nv_bfloat16* bt = Bs + (kc % NSTAGE) * TILE_H;

        #pragma unroll
        for (int ks = 0; ks < 2; ++ks) {             // two k16 steps per chunk
            const int k0 = ks * 16;

            uint32_t af[4][4];
            #pragma unroll
            for (int mt = 0; mt < 4; ++mt) {
                uint32_t addr = smem_addr_u32(
                    at + (warpM * 64 + mt * 16 + a_row) * PITCH + k0 + a_koff);
                LDMATRIX_X4(af[mt][0], af[mt][1], af[mt][2], af[mt][3], addr);
            }

            uint32_t bf[4][2];
            #pragma unroll
            for (int np = 0; np < 2; ++np) {         // each x4 covers 2 n-tiles
                uint32_t addr = smem_addr_u32(
                    bt + (warpN * 32 + np * 16 + b_nrow) * PITCH + k0 + b_koff);
                LDMATRIX_X4(bf[np * 2][0], bf[np * 2][1],
                            bf[np * 2 + 1][0], bf[np * 2 + 1][1], addr);
            }

            #pragma unroll
            for (int mt = 0; mt < 4; ++mt)
                #pragma unroll
                for (int nt = 0; nt < 4; ++nt)
                    MMA_BF16(acc[mt][nt][0], acc[mt][nt][1],
                             acc[mt][nt][2], acc[mt][nt][3],
                             af[mt][0], af[mt][1], af[mt][2], af[mt][3],
                             bf[nt][0], bf[nt][1]);
        }
    }

    // ------------------- fused epilogue -------------------
    const float t    = *tptr;
    const float sigT = 1.0f / (1.0f + __expf(-t));

    const int g  = lane >> 2;       // 0..7
    const int tq = lane & 3;        // 0..3

    float2 cpair[4];
    #pragma unroll
    for (int nt = 0; nt < 4; ++nt) {
        int col = bN + warpN * 32 + nt * 8 + 2 * tq;
        cpair[nt] = *reinterpret_cast<const float2*>(&g_c[col]);
    }

    #pragma unroll
    for (int mt = 0; mt < 4; ++mt) {
        const int r0 = bM + warpM * 64 + mt * 16 + g;
        #pragma unroll
        for (int nt = 0; nt < 4; ++nt) {
            const int col = bN + warpN * 32 + nt * 8 + 2 * tq;
            float2 o0, o1;
            {
                float d2 = fmaxf(acc[mt][nt][0] + cpair[nt].x, 0.0f);
                o0.x = __expf(sigT * __expf(-fsqrt_approx(d2)));
                d2 = fmaxf(acc[mt][nt][1] + cpair[nt].y, 0.0f);
                o0.y = __expf(sigT * __expf(-fsqrt_approx(d2)));
                d2 = fmaxf(acc[mt][nt][2] + cpair[nt].x, 0.0f);
                o1.x = __expf(sigT * __expf(-fsqrt_approx(d2)));
                d2 = fmaxf(acc[mt][nt][3] + cpair[nt].y, 0.0f);
                o1.y = __expf(sigT * __expf(-fsqrt_approx(d2)));
            }
            *reinterpret_cast<float2*>(&out[(size_t)r0 * NF + col])       = o0;
            *reinterpret_cast<float2*>(&out[(size_t)(r0 + 8) * NF + col]) = o1;
        }
    }
}

// ===========================================================================
// normalize: one block (128 threads) per row
// ===========================================================================
__global__ __launch_bounds__(128)
void normalize_kernel(float* __restrict__ out) {
    const int b    = blockIdx.x;        // 0..2047
    const int tid  = threadIdx.x;       // 0..127
    const int lane = tid & 31;
    const int w    = tid >> 5;
    float* rp = out + (size_t)b * NF;

    float4 v0 = *reinterpret_cast<float4*>(rp + tid * 4);
    float4 v1 = *reinterpret_cast<float4*>(rp + 512 + tid * 4);
    float s = (v0.x + v0.y) + (v0.z + v0.w) + (v1.x + v1.y) + (v1.z + v1.w);

    #pragma unroll
    for (int off = 16; off > 0; off >>= 1)
        s += __shfl_xor_sync(0xFFFFFFFFu, s, off);

    __shared__ float ws[4];
    if (lane == 0) ws[w] = s;
    __syncthreads();
    const float tot = (ws[0] + ws[1]) + (ws[2] + ws[3]);
    const float inv = 1.0f / tot;

    v0.x *= inv; v0.y *= inv; v0.z *= inv; v0.w *= inv;
    v1.x *= inv; v1.y *= inv; v1.z *= inv; v1.w *= inv;
    *reinterpret_cast<float4*>(rp + tid * 4)       = v0;
    *reinterpret_cast<float4*>(rp + 512 + tid * 4) = v1;
}

// ===========================================================================
extern "C" void kernel_launch(void* const* d_in, const int* in_sizes, int n_in,
                              void* d_out, int out_size) {
    const float* x     = (const float*)d_in[0];   // (2048, 256)
    const float* mu    = (const float*)d_in[1];   // (1024, 256)
    const float* sigma = (const float*)d_in[2];   // (1, 1024, 256)
    const float* temp  = (const float*)d_in[3];   // scalar
    float* out = (float*)d_out;                   // (2048, 1024)

    cudaFuncSetAttribute(gemm_mma_kernel,
                         cudaFuncAttributeMaxDynamicSharedMemorySize, SMEM_DYN);

    prep_kernel<<<384, 256>>>(x, mu, sigma);
    gemm_mma_kernel<<<dim3(NF / BN, BATCH / BM), 256, SMEM_DYN>>>(temp, out);
    normalize_kernel<<<BATCH, 128>>>(out);
}